// round 7
// baseline (speedup 1.0000x reference)
#include <cuda_runtime.h>

typedef unsigned long long ull;

#define BB 32
#define LL 4096
#define HH 128
#define H2 256
#define VV 32000
#define TOK 64
#define NTOK (BB*LL)
#define NBLK (LL/4)

// ---- packed-fp32 helpers ---------------------------------------------------
__device__ __forceinline__ ull pk2(float lo, float hi) {
    ull r; asm("mov.b64 %0, {%1, %2};" : "=l"(r) : "f"(lo), "f"(hi)); return r;
}
__device__ __forceinline__ void upk2(ull v, float& lo, float& hi) {
    asm("mov.b64 {%0, %1}, %2;" : "=f"(lo), "=f"(hi) : "l"(v));
}
__device__ __forceinline__ ull f2fma(ull a, ull b, ull c) {
    ull d; asm("fma.rn.f32x2 %0, %1, %2, %3;" : "=l"(d) : "l"(a), "l"(b), "l"(c)); return d;
}
__device__ __forceinline__ float wredux(float p) {
    p += __shfl_xor_sync(0xffffffffu, p, 16);
    p += __shfl_xor_sync(0xffffffffu, p, 8);
    p += __shfl_xor_sync(0xffffffffu, p, 4);
    p += __shfl_xor_sync(0xffffffffu, p, 2);
    p += __shfl_xor_sync(0xffffffffu, p, 1);
    return p;
}
__device__ __forceinline__ float dot4(float4 a, float4 b) {
    return fmaf(a.x, b.x, fmaf(a.y, b.y, fmaf(a.z, b.z, a.w * b.w)));
}

// Scratch (static device globals)
__device__ float g_k[(size_t)NTOK * HH];     // normalized kn, (B*L, H)
__device__ float g_kra[(size_t)NTOK * HH];   // RAW k, transposed (B, H, L)
__device__ float g_nrm[NTOK];                // norm_eff
__device__ float g_d6[(size_t)BB * NBLK * 8];// per-4-block pairwise dots
__device__ float g_read[BB * HH];
__device__ float g_r2[BB * HH];

// ---------------------------------------------------------------------------
// Kernel A: fused embed-gather -> MLP(relu) -> residual+LN -> k-projection
// smem = 112KB (16KB weight stages) => 2 CTAs/SM.
// ---------------------------------------------------------------------------
__global__ void __launch_bounds__(256) kA(
    const int* __restrict__ seq, const float* __restrict__ embed,
    const float* __restrict__ W1, const float* __restrict__ b1,
    const float* __restrict__ W2, const float* __restrict__ b2,
    const float* __restrict__ lng, const float* __restrict__ lnb,
    const float* __restrict__ Wkp)
{
    extern __shared__ float sm[];
    float* sH = sm;                 // 64 x 128   (8192 f)
    float* sW = sm + 8192;          // 4096 f (16KB stage)
    float* sA = sm + 12288;         // 64 x 256   (16384 f)
    __shared__ int sSeq[TOK];
    __shared__ float sInv[TOK];

    const int tid = threadIdx.x;
    const int t0  = blockIdx.x * TOK;
    if (tid < TOK) sSeq[tid] = seq[t0 + tid];
    __syncthreads();

    // gather embeddings
    {
        float4* d = (float4*)sH;
        const float4* e = (const float4*)embed;
        for (int idx = tid; idx < TOK * (HH / 4); idx += 256) {
            int r = idx >> 5;
            d[idx] = e[(size_t)sSeq[r] * (HH / 4) + (idx & 31)];
        }
    }
    __syncthreads();

    const int tx = tid & 15, ty = tid >> 4;

    // ---- GEMM1: A = relu(H @ W1 + b1)  (64x128x256), 8 stages of 16 rows
    ull accp[4][8];
#pragma unroll
    for (int r = 0; r < 4; r++)
#pragma unroll
        for (int c = 0; c < 8; c++) accp[r][c] = 0ULL;

    for (int kb = 0; kb < 8; kb++) {
        __syncthreads();
        {
            float4* d = (float4*)sW;
            const float4* s = (const float4*)W1;
            for (int idx = tid; idx < 16 * (H2 / 4); idx += 256) {
                int r = idx >> 6;
                d[idx] = s[(kb * 16 + r) * (H2 / 4) + (idx & 63)];
            }
        }
        __syncthreads();
#pragma unroll
        for (int kk = 0; kk < 16; kk++) {
            ull hd[4];
#pragma unroll
            for (int r = 0; r < 4; r++) {
                float hv = sH[(ty * 4 + r) * HH + kb * 16 + kk];
                hd[r] = pk2(hv, hv);
            }
#pragma unroll
            for (int q = 0; q < 4; q++) {
                ulonglong2 w = ((const ulonglong2*)sW)[kk * (H2 / 4) + q * 16 + tx];
#pragma unroll
                for (int r = 0; r < 4; r++) {
                    accp[r][q * 2 + 0] = f2fma(hd[r], w.x, accp[r][q * 2 + 0]);
                    accp[r][q * 2 + 1] = f2fma(hd[r], w.y, accp[r][q * 2 + 1]);
                }
            }
        }
    }
    __syncthreads();
    // bias + relu -> sA (64 x 256)
#pragma unroll
    for (int q = 0; q < 4; q++)
#pragma unroll
        for (int h = 0; h < 2; h++) {
            int c = q * 64 + tx * 4 + h * 2;
            float bb0 = b1[c], bb1 = b1[c + 1];
#pragma unroll
            for (int r = 0; r < 4; r++) {
                float lo, hi; upk2(accp[r][q * 2 + h], lo, hi);
                float v0 = lo + bb0, v1 = hi + bb1;
                sA[(ty * 4 + r) * H2 + c]     = v0 > 0.f ? v0 : 0.f;
                sA[(ty * 4 + r) * H2 + c + 1] = v1 > 0.f ? v1 : 0.f;
            }
        }

    // ---- GEMM2: F = A @ W2 + b2  (64x256x128), 8 stages of 32 rows
    ull accp2[4][4];
#pragma unroll
    for (int r = 0; r < 4; r++)
#pragma unroll
        for (int c = 0; c < 4; c++) accp2[r][c] = 0ULL;

    for (int kb = 0; kb < 8; kb++) {
        __syncthreads();
        {
            float4* d = (float4*)sW;
            const float4* s = (const float4*)W2;
            for (int idx = tid; idx < 32 * (HH / 4); idx += 256) {
                int r = idx >> 5;
                d[idx] = s[(kb * 32 + r) * (HH / 4) + (idx & 31)];
            }
        }
        __syncthreads();
#pragma unroll
        for (int kk = 0; kk < 32; kk++) {
            ull ad[4];
#pragma unroll
            for (int r = 0; r < 4; r++) {
                float av = sA[(ty * 4 + r) * H2 + kb * 32 + kk];
                ad[r] = pk2(av, av);
            }
#pragma unroll
            for (int q = 0; q < 2; q++) {
                ulonglong2 w = ((const ulonglong2*)sW)[kk * (HH / 4) + q * 16 + tx];
#pragma unroll
                for (int r = 0; r < 4; r++) {
                    accp2[r][q * 2 + 0] = f2fma(ad[r], w.x, accp2[r][q * 2 + 0]);
                    accp2[r][q * 2 + 1] = f2fma(ad[r], w.y, accp2[r][q * 2 + 1]);
                }
            }
        }
    }
    __syncthreads();

    // x = F + b2 + H -> sA (as 64 x 128)
#pragma unroll
    for (int q = 0; q < 2; q++)
#pragma unroll
        for (int h = 0; h < 2; h++) {
            int c = q * 64 + tx * 4 + h * 2;
            float bb0 = b2[c], bb1 = b2[c + 1];
#pragma unroll
            for (int r = 0; r < 4; r++) {
                int t = ty * 4 + r;
                float lo, hi; upk2(accp2[r][q * 2 + h], lo, hi);
                sA[t * HH + c]     = lo + bb0 + sH[t * HH + c];
                sA[t * HH + c + 1] = hi + bb1 + sH[t * HH + c + 1];
            }
        }
    __syncthreads();

    // LayerNorm per token -> sH
    {
        int warp = tid >> 5, lane = tid & 31;
        for (int tt = warp * 8; tt < warp * 8 + 8; tt++) {
            float4 x = ((const float4*)sA)[tt * 32 + lane];
            float s1 = x.x + x.y + x.z + x.w;
            float s2 = fmaf(x.x, x.x, fmaf(x.y, x.y, fmaf(x.z, x.z, x.w * x.w)));
#pragma unroll
            for (int o = 16; o; o >>= 1) {
                s1 += __shfl_xor_sync(0xffffffffu, s1, o);
                s2 += __shfl_xor_sync(0xffffffffu, s2, o);
            }
            float mu  = s1 * (1.f / HH);
            float var = s2 * (1.f / HH) - mu * mu;
            float rs  = rsqrtf(var + 1e-5f);
            float4 gg = ((const float4*)lng)[lane];
            float4 bb = ((const float4*)lnb)[lane];
            float4 o;
            o.x = (x.x - mu) * rs * gg.x + bb.x;
            o.y = (x.y - mu) * rs * gg.y + bb.y;
            o.z = (x.z - mu) * rs * gg.z + bb.z;
            o.w = (x.w - mu) * rs * gg.w + bb.w;
            ((float4*)sH)[tt * 32 + lane] = o;
        }
    }
    __syncthreads();

    // ---- GEMM3: K = HN @ Wkp  (64x128x128), 4 stages of 32 rows
    ull accp3[4][4];
#pragma unroll
    for (int r = 0; r < 4; r++)
#pragma unroll
        for (int c = 0; c < 4; c++) accp3[r][c] = 0ULL;

    for (int kb = 0; kb < 4; kb++) {
        __syncthreads();
        {
            float4* d = (float4*)sW;
            const float4* s = (const float4*)Wkp;
            for (int idx = tid; idx < 32 * (HH / 4); idx += 256) {
                int r = idx >> 5;
                d[idx] = s[(kb * 32 + r) * (HH / 4) + (idx & 31)];
            }
        }
        __syncthreads();
#pragma unroll
        for (int kk = 0; kk < 32; kk++) {
            ull hd[4];
#pragma unroll
            for (int r = 0; r < 4; r++) {
                float hv = sH[(ty * 4 + r) * HH + kb * 32 + kk];
                hd[r] = pk2(hv, hv);
            }
#pragma unroll
            for (int q = 0; q < 2; q++) {
                ulonglong2 w = ((const ulonglong2*)sW)[kk * (HH / 4) + q * 16 + tx];
#pragma unroll
                for (int r = 0; r < 4; r++) {
                    accp3[r][q * 2 + 0] = f2fma(hd[r], w.x, accp3[r][q * 2 + 0]);
                    accp3[r][q * 2 + 1] = f2fma(hd[r], w.y, accp3[r][q * 2 + 1]);
                }
            }
        }
    }
    // write raw K into sA (64 x 128)
#pragma unroll
    for (int q = 0; q < 2; q++)
#pragma unroll
        for (int h = 0; h < 2; h++) {
            int c = q * 64 + tx * 4 + h * 2;
#pragma unroll
            for (int r = 0; r < 4; r++) {
                float lo, hi; upk2(accp3[r][q * 2 + h], lo, hi);
                sA[(ty * 4 + r) * HH + c]     = lo;
                sA[(ty * 4 + r) * HH + c + 1] = hi;
            }
        }
    __syncthreads();

    // per-token norms
    {
        int warp = tid >> 5, lane = tid & 31;
        for (int tt = warp * 8; tt < warp * 8 + 8; tt++) {
            float4 x = ((const float4*)sA)[tt * 32 + lane];
            float ss = fmaf(x.x, x.x, fmaf(x.y, x.y, fmaf(x.z, x.z, x.w * x.w)));
#pragma unroll
            for (int o = 16; o; o >>= 1) ss += __shfl_xor_sync(0xffffffffu, ss, o);
            if (lane == 0) {
                float n = fmaxf(sqrtf(ss), 1e-12f);
                g_nrm[t0 + tt] = n;
                sInv[tt] = 1.f / n;
            }
        }
    }
    __syncthreads();

    // write transposed RAW k: g_kra[b][i][t]
    {
        int bb = t0 >> 12;          // / LL
        int l  = t0 & (LL - 1);
        float* dst = g_kra + (size_t)bb * HH * LL + l;
        for (int idx = tid; idx < TOK * HH; idx += 256) {
            int i  = idx >> 6;
            int tt = idx & 63;
            dst[(size_t)i * LL + tt] = sA[tt * HH + i];
        }
    }
    // write NORMALIZED kn
    {
        float4* gk = (float4*)g_k;
        const float4* s = (const float4*)sA;
        for (int idx = tid; idx < TOK * 32; idx += 256) {
            float inv = sInv[idx >> 5];
            float4 v = s[idx];
            v.x *= inv; v.y *= inv; v.z *= inv; v.w *= inv;
            gk[(size_t)t0 * 32 + idx] = v;
        }
    }
}

// ---------------------------------------------------------------------------
// Kernel P: per-4-block pairwise dots among kn rows.
// g_d6[blk] = {d01, d02, d03, d12, d13, d23, 0, 0}
// One warp per (b, blk).
// ---------------------------------------------------------------------------
__global__ void __launch_bounds__(256) kP()
{
    int w = blockIdx.x * 8 + (threadIdx.x >> 5);     // 0 .. BB*NBLK-1
    int lane = threadIdx.x & 31;
    int b = w >> 10;                                  // NBLK = 1024
    int blk = w & (NBLK - 1);
    const float4* kb4 = (const float4*)(g_k + ((size_t)b * LL + blk * 4) * HH) + lane;
    float4 r0 = __ldg(kb4);
    float4 r1 = __ldg(kb4 + 32);
    float4 r2 = __ldg(kb4 + 64);
    float4 r3 = __ldg(kb4 + 96);
    float d01 = wredux(dot4(r0, r1));
    float d02 = wredux(dot4(r0, r2));
    float d03 = wredux(dot4(r0, r3));
    float d12 = wredux(dot4(r1, r2));
    float d13 = wredux(dot4(r1, r3));
    float d23 = wredux(dot4(r2, r3));
    if (lane == 0) {
        float4* o = (float4*)(g_d6 + (size_t)w * 8);
        o[0] = make_float4(d01, d02, d03, d12);
        o[1] = make_float4(d13, d23, 0.f, 0.f);
    }
}

// ---------------------------------------------------------------------------
// Kernel B: delta-rule scan, 4-step blocked. One warp = one (batch,row).
// Within a block all four p_s = M.kn_s use the same M; corrections are fixed
// up with precomputed pairwise dots. The 4 butterflies interleave.
// ---------------------------------------------------------------------------
__global__ void __launch_bounds__(256) kScan()
{
    const int warp = threadIdx.x >> 5, lane = threadIdx.x & 31;
    const int b = blockIdx.x >> 4;
    const int i = ((blockIdx.x & 15) << 3) + warp;

    const float*      kbase = g_k + (size_t)b * LL * HH;
    const ulonglong2* kp    = (const ulonglong2*)kbase + lane;            // +32 per t
    const float4*     ap    = (const float4*)(g_kra + (size_t)(b * HH + i) * LL);  // +1 per block
    const float4*     dp    = (const float4*)(g_d6 + (size_t)b * NBLK * 8);        // +2 per block

    ull m01 = 0ULL, m23 = 0ULL;

    // prologue: block 0
    ulonglong2 k0 = __ldg(kp +  0), k1 = __ldg(kp + 32),
               k2 = __ldg(kp + 64), k3 = __ldg(kp + 96);
    float4 av = __ldg(ap);
    float4 da = __ldg(dp), db = __ldg(dp + 1);

    for (int blk = 0; blk < NBLK - 1; blk++) {
        // prefetch next block
        const ulonglong2* nk = kp + (size_t)(blk + 1) * 128;
        ulonglong2 n0 = __ldg(nk),      n1 = __ldg(nk + 32),
                   n2 = __ldg(nk + 64), n3 = __ldg(nk + 96);
        float4 nav = __ldg(ap + blk + 1);
        float4 nda = __ldg(dp + (blk + 1) * 2), ndb = __ldg(dp + (blk + 1) * 2 + 1);

        // partial dots vs current M
        float p0, p1, p2, p3;
        { ull u = f2fma(m01, k0.x, 0ULL); u = f2fma(m23, k0.y, u); float lo, hi; upk2(u, lo, hi); p0 = lo + hi; }
        { ull u = f2fma(m01, k1.x, 0ULL); u = f2fma(m23, k1.y, u); float lo, hi; upk2(u, lo, hi); p1 = lo + hi; }
        { ull u = f2fma(m01, k2.x, 0ULL); u = f2fma(m23, k2.y, u); float lo, hi; upk2(u, lo, hi); p2 = lo + hi; }
        { ull u = f2fma(m01, k3.x, 0ULL); u = f2fma(m23, k3.y, u); float lo, hi; upk2(u, lo, hi); p3 = lo + hi; }

        // four interleaved butterflies
#pragma unroll
        for (int o = 16; o; o >>= 1) {
            p0 += __shfl_xor_sync(0xffffffffu, p0, o);
            p1 += __shfl_xor_sync(0xffffffffu, p1, o);
            p2 += __shfl_xor_sync(0xffffffffu, p2, o);
            p3 += __shfl_xor_sync(0xffffffffu, p3, o);
        }

        // sequential fixups (exact reassociation of the true recurrence)
        float c0 = av.x - p0;
        float c1 = fmaf(-c0, da.x, av.y - p1);
        float c2 = fmaf(-c1, da.w, fmaf(-c0, da.y, av.z - p2));
        float c3 = fmaf(-c2, db.y, fmaf(-c1, db.x, fmaf(-c0, da.z, av.w - p3)));

        // rank-4 update of M-row
        ull cd;
        cd = pk2(c0, c0); m01 = f2fma(cd, k0.x, m01); m23 = f2fma(cd, k0.y, m23);
        cd = pk2(c1, c1); m01 = f2fma(cd, k1.x, m01); m23 = f2fma(cd, k1.y, m23);
        cd = pk2(c2, c2); m01 = f2fma(cd, k2.x, m01); m23 = f2fma(cd, k2.y, m23);
        cd = pk2(c3, c3); m01 = f2fma(cd, k3.x, m01); m23 = f2fma(cd, k3.y, m23);

        k0 = n0; k1 = n1; k2 = n2; k3 = n3; av = nav; da = nda; db = ndb;
    }

    // final block (t = L-4..L-1): steps L-4..L-2 are scan steps, t=L-1 is q.
    float p0, p1, p2, p3;
    { ull u = f2fma(m01, k0.x, 0ULL); u = f2fma(m23, k0.y, u); float lo, hi; upk2(u, lo, hi); p0 = lo + hi; }
    { ull u = f2fma(m01, k1.x, 0ULL); u = f2fma(m23, k1.y, u); float lo, hi; upk2(u, lo, hi); p1 = lo + hi; }
    { ull u = f2fma(m01, k2.x, 0ULL); u = f2fma(m23, k2.y, u); float lo, hi; upk2(u, lo, hi); p2 = lo + hi; }
    { ull u = f2fma(m01, k3.x, 0ULL); u = f2fma(m23, k3.y, u); float lo, hi; upk2(u, lo, hi); p3 = lo + hi; }
#pragma unroll
    for (int o = 16; o; o >>= 1) {
        p0 += __shfl_xor_sync(0xffffffffu, p0, o);
        p1 += __shfl_xor_sync(0xffffffffu, p1, o);
        p2 += __shfl_xor_sync(0xffffffffu, p2, o);
        p3 += __shfl_xor_sync(0xffffffffu, p3, o);
    }
    float c0 = av.x - p0;
    float c1 = fmaf(-c0, da.x, av.y - p1);
    float c2 = fmaf(-c1, da.w, fmaf(-c0, da.y, av.z - p2));
    // M_final . kn_{L-1} = p3 + c0*d03 + c1*d13 + c2*d23 ; read = nrm * that
    float r = fmaf(c2, db.y, fmaf(c1, db.x, fmaf(c0, da.z, p3)));
    float nrm = __ldg(&g_nrm[b * LL + (LL - 1)]);
    if (lane == 0) g_read[b * HH + i] = r * nrm;
}

// ---------------------------------------------------------------------------
// Kernel C: r2 = read @ Wrp + brp   (32 x 128)
// ---------------------------------------------------------------------------
__global__ void __launch_bounds__(256) kC(const float* __restrict__ Wrp,
                                          const float* __restrict__ brp)
{
    int idx = blockIdx.x * 256 + threadIdx.x;
    if (idx >= BB * HH) return;
    int b = idx >> 7, d = idx & 127;
    float s = brp[d];
#pragma unroll 8
    for (int h = 0; h < HH; h++)
        s = fmaf(__ldg(&g_read[b * HH + h]), __ldg(&Wrp[h * HH + d]), s);
    g_r2[idx] = s;
}

// ---------------------------------------------------------------------------
// Kernel D: out = r2 @ Wout + bout   (32 x 32000)
// ---------------------------------------------------------------------------
__global__ void __launch_bounds__(256) kD(const float* __restrict__ Wout,
                                          const float* __restrict__ bout,
                                          float* __restrict__ out)
{
    __shared__ float sr[BB * HH];
    for (int idx = threadIdx.x; idx < BB * HH; idx += 256) sr[idx] = g_r2[idx];
    __syncthreads();
    int v = blockIdx.x * 256 + threadIdx.x;
    if (v >= VV) return;

    float acc[BB];
#pragma unroll
    for (int b = 0; b < BB; b++) acc[b] = 0.f;

#pragma unroll 1
    for (int h0 = 0; h0 < HH; h0 += 8) {
        float wv[8];
#pragma unroll
        for (int u = 0; u < 8; u++)
            wv[u] = __ldg(&Wout[(size_t)(h0 + u) * VV + v]);
#pragma unroll
        for (int u = 0; u < 8; u++)
#pragma unroll
            for (int b = 0; b < BB; b++)
                acc[b] = fmaf(sr[b * HH + h0 + u], wv[u], acc[b]);
    }
    float bo = __ldg(&bout[v]);
#pragma unroll
    for (int b = 0; b < BB; b++)
        out[(size_t)b * VV + v] = acc[b] + bo;
}

// ---------------------------------------------------------------------------
extern "C" void kernel_launch(void* const* d_in, const int* in_sizes, int n_in,
                              void* d_out, int out_size)
{
    const int*   seq   = (const int*)d_in[0];
    const float* embed = (const float*)d_in[1];
    const float* W1    = (const float*)d_in[2];
    const float* b1    = (const float*)d_in[3];
    const float* W2    = (const float*)d_in[4];
    const float* b2    = (const float*)d_in[5];
    const float* lng   = (const float*)d_in[6];
    const float* lnb   = (const float*)d_in[7];
    const float* Wkp   = (const float*)d_in[8];
    const float* Wrp   = (const float*)d_in[9];
    const float* brp   = (const float*)d_in[10];
    const float* Wout  = (const float*)d_in[11];
    const float* bout  = (const float*)d_in[12];
    float* out = (float*)d_out;

    cudaFuncSetAttribute(kA, cudaFuncAttributeMaxDynamicSharedMemorySize, 114688);

    kA<<<NTOK / TOK, 256, 114688>>>(seq, embed, W1, b1, W2, b2, lng, lnb, Wkp);
    kP<<<(BB * NBLK) / 8, 256>>>();
    kScan<<<(BB * HH) / 8, 256>>>();
    kC<<<(BB * HH + 255) / 256, 256>>>(Wrp, brp);
    kD<<<(VV + 255) / 256, 256>>>(Wout, bout, out);
}

// round 8
// speedup vs baseline: 1.0031x; 1.0031x over previous
#include <cuda_runtime.h>

typedef unsigned long long ull;

#define BB 32
#define LL 4096
#define HH 128
#define H2 256
#define VV 32000
#define TOK 64
#define NTOK (BB*LL)
#define CH 32              // scan chunk (steps staged per double-buffer slot)

// ---- packed-fp32 helpers ---------------------------------------------------
__device__ __forceinline__ ull pk2(float lo, float hi) {
    ull r; asm("mov.b64 %0, {%1, %2};" : "=l"(r) : "f"(lo), "f"(hi)); return r;
}
__device__ __forceinline__ void upk2(ull v, float& lo, float& hi) {
    asm("mov.b64 {%0, %1}, %2;" : "=f"(lo), "=f"(hi) : "l"(v));
}
__device__ __forceinline__ ull f2fma(ull a, ull b, ull c) {
    ull d; asm("fma.rn.f32x2 %0, %1, %2, %3;" : "=l"(d) : "l"(a), "l"(b), "l"(c)); return d;
}
__device__ __forceinline__ void cpasync16(unsigned s, const void* g) {
    asm volatile("cp.async.ca.shared.global [%0], [%1], 16;" :: "r"(s), "l"(g));
}
__device__ __forceinline__ void cpcommit() { asm volatile("cp.async.commit_group;"); }
__device__ __forceinline__ void cpwait0()  { asm volatile("cp.async.wait_group 0;"); }

// Scratch (static device globals)
__device__ float g_k[(size_t)NTOK * HH];   // normalized kn, (B*L, H)
__device__ float g_nrm[NTOK];              // norm_eff
__device__ float g_read[BB * HH];
__device__ float g_r2[BB * HH];

// ---------------------------------------------------------------------------
// Kernel A (R6 version, unchanged): fused gather -> MLP -> LN -> k-proj
// ---------------------------------------------------------------------------
__global__ void __launch_bounds__(256) kA(
    const int* __restrict__ seq, const float* __restrict__ embed,
    const float* __restrict__ W1, const float* __restrict__ b1,
    const float* __restrict__ W2, const float* __restrict__ b2,
    const float* __restrict__ lng, const float* __restrict__ lnb,
    const float* __restrict__ Wkp)
{
    extern __shared__ float sm[];
    float* sH = sm;               // 64 x 128
    float* sW = sm + TOK * HH;    // 8192 f weight stage
    float* sA = sW + 8192;        // 64 x 256
    __shared__ int sSeq[TOK];
    __shared__ float sInv[TOK];

    const int tid = threadIdx.x;
    const int t0  = blockIdx.x * TOK;
    if (tid < TOK) sSeq[tid] = seq[t0 + tid];
    __syncthreads();

    {
        float4* d = (float4*)sH;
        const float4* e = (const float4*)embed;
        for (int idx = tid; idx < TOK * (HH / 4); idx += 256) {
            int r = idx >> 5;
            d[idx] = e[(size_t)sSeq[r] * (HH / 4) + (idx & 31)];
        }
    }
    __syncthreads();

    const int tx = tid & 15, ty = tid >> 4;

    // GEMM1
    ull accp[4][8];
#pragma unroll
    for (int r = 0; r < 4; r++)
#pragma unroll
        for (int c = 0; c < 8; c++) accp[r][c] = 0ULL;

    for (int kb = 0; kb < 4; kb++) {
        __syncthreads();
        {
            float4* d = (float4*)sW;
            const float4* s = (const float4*)W1;
            for (int idx = tid; idx < 32 * (H2 / 4); idx += 256) {
                int r = idx >> 6;
                d[idx] = s[(kb * 32 + r) * (H2 / 4) + (idx & 63)];
            }
        }
        __syncthreads();
#pragma unroll
        for (int kk = 0; kk < 32; kk++) {
            ull hd[4];
#pragma unroll
            for (int r = 0; r < 4; r++) {
                float hv = sH[(ty * 4 + r) * HH + kb * 32 + kk];
                hd[r] = pk2(hv, hv);
            }
#pragma unroll
            for (int q = 0; q < 4; q++) {
                ulonglong2 w = ((const ulonglong2*)sW)[kk * (H2 / 4) + q * 16 + tx];
#pragma unroll
                for (int r = 0; r < 4; r++) {
                    accp[r][q * 2 + 0] = f2fma(hd[r], w.x, accp[r][q * 2 + 0]);
                    accp[r][q * 2 + 1] = f2fma(hd[r], w.y, accp[r][q * 2 + 1]);
                }
            }
        }
    }
#pragma unroll
    for (int q = 0; q < 4; q++)
#pragma unroll
        for (int h = 0; h < 2; h++) {
            int c = q * 64 + tx * 4 + h * 2;
            float bb0 = b1[c], bb1 = b1[c + 1];
#pragma unroll
            for (int r = 0; r < 4; r++) {
                float lo, hi; upk2(accp[r][q * 2 + h], lo, hi);
                float v0 = lo + bb0, v1 = hi + bb1;
                sA[(ty * 4 + r) * H2 + c]     = v0 > 0.f ? v0 : 0.f;
                sA[(ty * 4 + r) * H2 + c + 1] = v1 > 0.f ? v1 : 0.f;
            }
        }

    // GEMM2
    ull accp2[4][4];
#pragma unroll
    for (int r = 0; r < 4; r++)
#pragma unroll
        for (int c = 0; c < 4; c++) accp2[r][c] = 0ULL;

    for (int kb = 0; kb < 4; kb++) {
        __syncthreads();
        {
            float4* d = (float4*)sW;
            const float4* s = (const float4*)W2;
            for (int idx = tid; idx < 64 * (HH / 4); idx += 256) {
                int r = idx >> 5;
                d[idx] = s[(kb * 64 + r) * (HH / 4) + (idx & 31)];
            }
        }
        __syncthreads();
#pragma unroll
        for (int kk = 0; kk < 64; kk++) {
            ull ad[4];
#pragma unroll
            for (int r = 0; r < 4; r++) {
                float av = sA[(ty * 4 + r) * H2 + kb * 64 + kk];
                ad[r] = pk2(av, av);
            }
#pragma unroll
            for (int q = 0; q < 2; q++) {
                ulonglong2 w = ((const ulonglong2*)sW)[kk * (HH / 4) + q * 16 + tx];
#pragma unroll
                for (int r = 0; r < 4; r++) {
                    accp2[r][q * 2 + 0] = f2fma(ad[r], w.x, accp2[r][q * 2 + 0]);
                    accp2[r][q * 2 + 1] = f2fma(ad[r], w.y, accp2[r][q * 2 + 1]);
                }
            }
        }
    }
    __syncthreads();

#pragma unroll
    for (int q = 0; q < 2; q++)
#pragma unroll
        for (int h = 0; h < 2; h++) {
            int c = q * 64 + tx * 4 + h * 2;
            float bb0 = b2[c], bb1 = b2[c + 1];
#pragma unroll
            for (int r = 0; r < 4; r++) {
                int t = ty * 4 + r;
                float lo, hi; upk2(accp2[r][q * 2 + h], lo, hi);
                sA[t * HH + c]     = lo + bb0 + sH[t * HH + c];
                sA[t * HH + c + 1] = hi + bb1 + sH[t * HH + c + 1];
            }
        }
    __syncthreads();

    // LayerNorm -> sH
    {
        int warp = tid >> 5, lane = tid & 31;
        for (int tt = warp * 8; tt < warp * 8 + 8; tt++) {
            float4 x = ((const float4*)sA)[tt * 32 + lane];
            float s1 = x.x + x.y + x.z + x.w;
            float s2 = fmaf(x.x, x.x, fmaf(x.y, x.y, fmaf(x.z, x.z, x.w * x.w)));
#pragma unroll
            for (int o = 16; o; o >>= 1) {
                s1 += __shfl_xor_sync(0xffffffffu, s1, o);
                s2 += __shfl_xor_sync(0xffffffffu, s2, o);
            }
            float mu  = s1 * (1.f / HH);
            float var = s2 * (1.f / HH) - mu * mu;
            float rs  = rsqrtf(var + 1e-5f);
            float4 gg = ((const float4*)lng)[lane];
            float4 bb = ((const float4*)lnb)[lane];
            float4 o;
            o.x = (x.x - mu) * rs * gg.x + bb.x;
            o.y = (x.y - mu) * rs * gg.y + bb.y;
            o.z = (x.z - mu) * rs * gg.z + bb.z;
            o.w = (x.w - mu) * rs * gg.w + bb.w;
            ((float4*)sH)[tt * 32 + lane] = o;
        }
    }
    __syncthreads();

    // GEMM3
    ull accp3[4][4];
#pragma unroll
    for (int r = 0; r < 4; r++)
#pragma unroll
        for (int c = 0; c < 4; c++) accp3[r][c] = 0ULL;

    for (int kb = 0; kb < 2; kb++) {
        __syncthreads();
        {
            float4* d = (float4*)sW;
            const float4* s = (const float4*)Wkp;
            for (int idx = tid; idx < 64 * (HH / 4); idx += 256) {
                int r = idx >> 5;
                d[idx] = s[(kb * 64 + r) * (HH / 4) + (idx & 31)];
            }
        }
        __syncthreads();
#pragma unroll
        for (int kk = 0; kk < 64; kk++) {
            ull hd[4];
#pragma unroll
            for (int r = 0; r < 4; r++) {
                float hv = sH[(ty * 4 + r) * HH + kb * 64 + kk];
                hd[r] = pk2(hv, hv);
            }
#pragma unroll
            for (int q = 0; q < 2; q++) {
                ulonglong2 w = ((const ulonglong2*)sW)[kk * (HH / 4) + q * 16 + tx];
#pragma unroll
                for (int r = 0; r < 4; r++) {
                    accp3[r][q * 2 + 0] = f2fma(hd[r], w.x, accp3[r][q * 2 + 0]);
                    accp3[r][q * 2 + 1] = f2fma(hd[r], w.y, accp3[r][q * 2 + 1]);
                }
            }
        }
    }
#pragma unroll
    for (int q = 0; q < 2; q++)
#pragma unroll
        for (int h = 0; h < 2; h++) {
            int c = q * 64 + tx * 4 + h * 2;
#pragma unroll
            for (int r = 0; r < 4; r++) {
                float lo, hi; upk2(accp3[r][q * 2 + h], lo, hi);
                sA[(ty * 4 + r) * HH + c]     = lo;
                sA[(ty * 4 + r) * HH + c + 1] = hi;
            }
        }
    __syncthreads();

    // norms
    {
        int warp = tid >> 5, lane = tid & 31;
        for (int tt = warp * 8; tt < warp * 8 + 8; tt++) {
            float4 x = ((const float4*)sA)[tt * 32 + lane];
            float ss = fmaf(x.x, x.x, fmaf(x.y, x.y, fmaf(x.z, x.z, x.w * x.w)));
#pragma unroll
            for (int o = 16; o; o >>= 1) ss += __shfl_xor_sync(0xffffffffu, ss, o);
            if (lane == 0) {
                float n = fmaxf(sqrtf(ss), 1e-12f);
                g_nrm[t0 + tt] = n;
                sInv[tt] = 1.f / n;
            }
        }
    }
    __syncthreads();

    {
        float4* gk = (float4*)g_k;
        const float4* s = (const float4*)sA;
        for (int idx = tid; idx < TOK * 32; idx += 256) {
            float inv = sInv[idx >> 5];
            float4 v = s[idx];
            v.x *= inv; v.y *= inv; v.z *= inv; v.w *= inv;
            gk[(size_t)t0 * 32 + idx] = v;
        }
    }
}

// ---------------------------------------------------------------------------
// Kernel B v3: smem-staged delta-rule scan.
// 4 CTAs per batch (128 CTAs x 256 thr). CTA owns 32 rows: warp w -> rows
// q*32 + w*4 + g (g = lane>>3), lane segment s = lane&7 holds elements
// [s*16, s*16+16) of each of its row's M-state (8 x f32x2 regs).
// kn chunks (32 steps, 16KB) + nrm chunks double-buffered via cp.async.
// raw k_i recovered as kn[t][row] * nrm[t] (exact: kn*nrm == raw k).
// ---------------------------------------------------------------------------
__global__ void __launch_bounds__(256) kScan()
{
    __shared__ float sKn[2][CH * HH];   // 2 x 16KB
    __shared__ float sNr[2][CH];

    const int tid = threadIdx.x;
    const int b  = blockIdx.x >> 2;
    const int qq = blockIdx.x & 3;
    const int w = tid >> 5, lane = tid & 31;
    const int g = lane >> 3, s = lane & 7;
    const int row = qq * 32 + w * 4 + g;

    const float* kb = g_k + (size_t)b * LL * HH;
    const float* nb = g_nrm + b * LL;

    // stage chunk 0
    {
        unsigned dk = (unsigned)__cvta_generic_to_shared(&sKn[0][0]);
#pragma unroll
        for (int j = 0; j < 4; j++)
            cpasync16(dk + (unsigned)(tid + j * 256) * 16, kb + (tid + j * 256) * 4);
        if (tid < 8) {
            unsigned dn = (unsigned)__cvta_generic_to_shared(&sNr[0][0]);
            cpasync16(dn + (unsigned)tid * 16, nb + tid * 4);
        }
        cpcommit();
        cpwait0();
    }
    __syncthreads();

    ull m[8];
#pragma unroll
    for (int j = 0; j < 8; j++) m[j] = 0ULL;

    for (int c = 0; c < LL / CH; c++) {
        const int cur = c & 1;
        if (c < LL / CH - 1) {
            unsigned dk = (unsigned)__cvta_generic_to_shared(&sKn[cur ^ 1][0]);
            const float* src = kb + (size_t)(c + 1) * CH * HH;
#pragma unroll
            for (int j = 0; j < 4; j++)
                cpasync16(dk + (unsigned)(tid + j * 256) * 16, src + (tid + j * 256) * 4);
            if (tid < 8) {
                unsigned dn = (unsigned)__cvta_generic_to_shared(&sNr[cur ^ 1][0]);
                cpasync16(dn + (unsigned)tid * 16, nb + (c + 1) * CH + tid * 4);
            }
            cpcommit();
        }

        const float* kc = &sKn[cur][0];
        const float* nc = &sNr[cur][0];
        const int nsteps = (c == LL / CH - 1) ? CH - 1 : CH;   // last chunk: t=L-1 is q

        for (int tl = 0; tl < nsteps; tl++) {
            const ulonglong2* kl = (const ulonglong2*)(kc + tl * HH + s * 16);
            ulonglong2 k0 = kl[0], k1 = kl[1], k2 = kl[2], k3 = kl[3];
            float kr = kc[tl * HH + row];
            float nr = nc[tl];

            ull u0 = f2fma(m[0], k0.x, 0ULL); u0 = f2fma(m[1], k0.y, u0);
            u0 = f2fma(m[2], k1.x, u0);       u0 = f2fma(m[3], k1.y, u0);
            ull u1 = f2fma(m[4], k2.x, 0ULL); u1 = f2fma(m[5], k2.y, u1);
            u1 = f2fma(m[6], k3.x, u1);       u1 = f2fma(m[7], k3.y, u1);
            float a0, a1, b0, b1; upk2(u0, a0, a1); upk2(u1, b0, b1);
            float p = (a0 + a1) + (b0 + b1);
            p += __shfl_xor_sync(0xffffffffu, p, 4);
            p += __shfl_xor_sync(0xffffffffu, p, 2);
            p += __shfl_xor_sync(0xffffffffu, p, 1);

            float cc = fmaf(kr, nr, -p);       // raw k_row - (M.kn)_row
            ull cd = pk2(cc, cc);
            m[0] = f2fma(cd, k0.x, m[0]); m[1] = f2fma(cd, k0.y, m[1]);
            m[2] = f2fma(cd, k1.x, m[2]); m[3] = f2fma(cd, k1.y, m[3]);
            m[4] = f2fma(cd, k2.x, m[4]); m[5] = f2fma(cd, k2.y, m[5]);
            m[6] = f2fma(cd, k3.x, m[6]); m[7] = f2fma(cd, k3.y, m[7]);
        }

        if (c < LL / CH - 1) cpwait0();
        __syncthreads();
    }

    // final: q = kn[L-1] * nrm[L-1] -> read_row = nrm * (M . kn[L-1])
    {
        const float* kc = &sKn[1][0];   // chunk 127 lives in buffer 1
        const ulonglong2* kl = (const ulonglong2*)(kc + (CH - 1) * HH + s * 16);
        ulonglong2 k0 = kl[0], k1 = kl[1], k2 = kl[2], k3 = kl[3];
        float nr = sNr[1][CH - 1];
        ull u0 = f2fma(m[0], k0.x, 0ULL); u0 = f2fma(m[1], k0.y, u0);
        u0 = f2fma(m[2], k1.x, u0);       u0 = f2fma(m[3], k1.y, u0);
        ull u1 = f2fma(m[4], k2.x, 0ULL); u1 = f2fma(m[5], k2.y, u1);
        u1 = f2fma(m[6], k3.x, u1);       u1 = f2fma(m[7], k3.y, u1);
        float a0, a1, b0, b1; upk2(u0, a0, a1); upk2(u1, b0, b1);
        float p = (a0 + a1) + (b0 + b1);
        p += __shfl_xor_sync(0xffffffffu, p, 4);
        p += __shfl_xor_sync(0xffffffffu, p, 2);
        p += __shfl_xor_sync(0xffffffffu, p, 1);
        if (s == 0) g_read[b * HH + row] = p * nr;
    }
}

// ---------------------------------------------------------------------------
// Kernel C: r2 = read @ Wrp + brp   (32 x 128)
// ---------------------------------------------------------------------------
__global__ void __launch_bounds__(256) kC(const float* __restrict__ Wrp,
                                          const float* __restrict__ brp)
{
    int idx = blockIdx.x * 256 + threadIdx.x;
    if (idx >= BB * HH) return;
    int b = idx >> 7, d = idx & 127;
    float s = brp[d];
#pragma unroll 8
    for (int h = 0; h < HH; h++)
        s = fmaf(__ldg(&g_read[b * HH + h]), __ldg(&Wrp[h * HH + d]), s);
    g_r2[idx] = s;
}

// ---------------------------------------------------------------------------
// Kernel D: out = r2 @ Wout + bout   (32 x 32000)
// ---------------------------------------------------------------------------
__global__ void __launch_bounds__(256) kD(const float* __restrict__ Wout,
                                          const float* __restrict__ bout,
                                          float* __restrict__ out)
{
    __shared__ float sr[BB * HH];
    for (int idx = threadIdx.x; idx < BB * HH; idx += 256) sr[idx] = g_r2[idx];
    __syncthreads();
    int v = blockIdx.x * 256 + threadIdx.x;
    if (v >= VV) return;

    float acc[BB];
#pragma unroll
    for (int b = 0; b < BB; b++) acc[b] = 0.f;

#pragma unroll 1
    for (int h0 = 0; h0 < HH; h0 += 8) {
        float wv[8];
#pragma unroll
        for (int u = 0; u < 8; u++)
            wv[u] = __ldg(&Wout[(size_t)(h0 + u) * VV + v]);
#pragma unroll
        for (int u = 0; u < 8; u++)
#pragma unroll
            for (int b = 0; b < BB; b++)
                acc[b] = fmaf(sr[b * HH + h0 + u], wv[u], acc[b]);
    }
    float bo = __ldg(&bout[v]);
#pragma unroll
    for (int b = 0; b < BB; b++)
        out[(size_t)b * VV + v] = acc[b] + bo;
}

// ---------------------------------------------------------------------------
extern "C" void kernel_launch(void* const* d_in, const int* in_sizes, int n_in,
                              void* d_out, int out_size)
{
    const int*   seq   = (const int*)d_in[0];
    const float* embed = (const float*)d_in[1];
    const float* W1    = (const float*)d_in[2];
    const float* b1    = (const float*)d_in[3];
    const float* W2    = (const float*)d_in[4];
    const float* b2    = (const float*)d_in[5];
    const float* lng   = (const float*)d_in[6];
    const float* lnb   = (const float*)d_in[7];
    const float* Wkp   = (const float*)d_in[8];
    const float* Wrp   = (const float*)d_in[9];
    const float* brp   = (const float*)d_in[10];
    const float* Wout  = (const float*)d_in[11];
    const float* bout  = (const float*)d_in[12];
    float* out = (float*)d_out;

    cudaFuncSetAttribute(kA, cudaFuncAttributeMaxDynamicSharedMemorySize, 131072);

    kA<<<NTOK / TOK, 256, 131072>>>(seq, embed, W1, b1, W2, b2, lng, lnb, Wkp);
    kScan<<<BB * 4, 256>>>();
    kC<<<(BB * HH + 255) / 256, 256>>>(Wrp, brp);
    kD<<<(VV + 255) / 256, 256>>>(Wout, bout, out);
}

// round 10
// speedup vs baseline: 1.1217x; 1.1182x over previous
#include <cuda_runtime.h>

typedef unsigned long long ull;

#define BB 32
#define LL 4096
#define HH 128
#define H2 256
#define VV 32000
#define TOK 64
#define NTOK (BB*LL)

// ---- helpers ---------------------------------------------------------------
__device__ __forceinline__ ull pk2(float lo, float hi) {
    ull r; asm("mov.b64 %0, {%1, %2};" : "=l"(r) : "f"(lo), "f"(hi)); return r;
}
__device__ __forceinline__ void upk2(ull v, float& lo, float& hi) {
    asm("mov.b64 {%0, %1}, %2;" : "=f"(lo), "=f"(hi) : "l"(v));
}
__device__ __forceinline__ ull f2fma(ull a, ull b, ull c) {
    ull d; asm("fma.rn.f32x2 %0, %1, %2, %3;" : "=l"(d) : "l"(a), "l"(b), "l"(c)); return d;
}
__device__ __forceinline__ void cpasync16(unsigned s, const void* g) {
    asm volatile("cp.async.ca.shared.global [%0], [%1], 16;" :: "r"(s), "l"(g));
}
__device__ __forceinline__ void cpcommit() { asm volatile("cp.async.commit_group;"); }
__device__ __forceinline__ void cpwait1()  { asm volatile("cp.async.wait_group 1;"); }
__device__ __forceinline__ void cpwait0()  { asm volatile("cp.async.wait_group 0;"); }

// Scratch
__device__ float g_k[(size_t)NTOK * HH];   // normalized kn, (B*L, H)
__device__ float g_nrm[NTOK];              // norm_eff
__device__ float g_read[BB * HH];
__device__ float g_r2[BB * HH];

// ---------------------------------------------------------------------------
// Kernel A v3: fused gather -> MLP(relu) -> residual+LN -> k-proj.
// smem 96KB => 2 CTAs/SM (4 warps/SMSP). All weight stages (32 k-rows x 128
// cols = 16KB) are cp.async DOUBLE-BUFFERED: stage kb+1 loads while kb
// computes. GEMM1+GEMM2 split into two 128-col/128-k halves so the
// activation slab is 64x128 (GEMM2 accumulator lives in registers across
// halves; summation order identical to before).
// ---------------------------------------------------------------------------
__global__ void __launch_bounds__(256, 2) kA(
    const int* __restrict__ seq, const float* __restrict__ embed,
    const float* __restrict__ W1, const float* __restrict__ b1,
    const float* __restrict__ W2, const float* __restrict__ b2,
    const float* __restrict__ lng, const float* __restrict__ lnb,
    const float* __restrict__ Wkp)
{
    extern __shared__ float sm[];
    float* sH = sm;              // 64 x 128 (32KB)
    float* sA = sm + 8192;       // 64 x 128 (32KB)
    float* sW = sm + 16384;      // 2 x 4096 (2 x 16KB stage buffers)
    __shared__ int sSeq[TOK];
    __shared__ float sInv[TOK];

    const int tid = threadIdx.x;
    const int t0  = blockIdx.x * TOK;
    if (tid < TOK) sSeq[tid] = seq[t0 + tid];
    __syncthreads();

    // gather embeddings
    {
        float4* d = (float4*)sH;
        const float4* e = (const float4*)embed;
        for (int idx = tid; idx < TOK * (HH / 4); idx += 256) {
            int r = idx >> 5;
            d[idx] = e[(size_t)sSeq[r] * (HH / 4) + (idx & 31)];
        }
    }
    __syncthreads();

    const int tx = tid & 15, ty = tid >> 4;
    const unsigned swb = (unsigned)__cvta_generic_to_shared(sW);

    float acc2[4][8];                      // GEMM2 (F) accumulator, both halves
#pragma unroll
    for (int r = 0; r < 4; r++)
#pragma unroll
        for (int c = 0; c < 8; c++) acc2[r][c] = 0.f;

    for (int hh = 0; hh < 2; hh++) {
        // ---- GEMM1 half: A[:,hh*128..] = H @ W1[:, hh*128..]  (64x128x128)
        float acc[4][8];
#pragma unroll
        for (int r = 0; r < 4; r++)
#pragma unroll
            for (int c = 0; c < 8; c++) acc[r][c] = 0.f;

        // prologue: stage 0 (rows 0..31)
        {
            const float4* s = (const float4*)W1;   // row = 64 float4
#pragma unroll
            for (int j = 0; j < 4; j++) {
                int idx = tid + j * 256;
                cpasync16(swb + (unsigned)idx * 16,
                          s + (size_t)(idx >> 5) * 64 + hh * 32 + (idx & 31));
            }
            cpcommit();
        }
        for (int kb = 0; kb < 4; kb++) {
            if (kb < 3) {
                const float4* s = (const float4*)W1;
                unsigned dst = swb + ((kb + 1) & 1) * 16384u;
#pragma unroll
                for (int j = 0; j < 4; j++) {
                    int idx = tid + j * 256;
                    cpasync16(dst + (unsigned)idx * 16,
                              s + (size_t)((kb + 1) * 32 + (idx >> 5)) * 64 + hh * 32 + (idx & 31));
                }
                cpcommit();
                cpwait1();
            } else cpwait0();
            __syncthreads();
            const float* wb = sW + (kb & 1) * 4096;
#pragma unroll
            for (int kk = 0; kk < 32; kk++) {
                float hv[4];
#pragma unroll
                for (int r = 0; r < 4; r++) hv[r] = sH[(ty * 4 + r) * HH + kb * 32 + kk];
#pragma unroll
                for (int q = 0; q < 2; q++) {
                    float4 w = ((const float4*)wb)[kk * 32 + q * 16 + tx];
#pragma unroll
                    for (int r = 0; r < 4; r++) {
                        acc[r][q * 4 + 0] = fmaf(hv[r], w.x, acc[r][q * 4 + 0]);
                        acc[r][q * 4 + 1] = fmaf(hv[r], w.y, acc[r][q * 4 + 1]);
                        acc[r][q * 4 + 2] = fmaf(hv[r], w.z, acc[r][q * 4 + 2]);
                        acc[r][q * 4 + 3] = fmaf(hv[r], w.w, acc[r][q * 4 + 3]);
                    }
                }
            }
            __syncthreads();
        }
        // bias + relu -> sA (64 x 128, local cols = global hh*128+c)
#pragma unroll
        for (int q = 0; q < 2; q++)
#pragma unroll
            for (int u = 0; u < 4; u++) {
                int c = q * 64 + tx * 4 + u;
                float bb = b1[hh * 128 + c];
#pragma unroll
                for (int r = 0; r < 4; r++) {
                    float v = acc[r][q * 4 + u] + bb;
                    sA[(ty * 4 + r) * HH + c] = v > 0.f ? v : 0.f;
                }
            }
        __syncthreads();

        // ---- GEMM2 half: F += A_half @ W2[hh*128.., :]  (64x128x128)
        {
            const float4* s = (const float4*)W2;   // row = 32 float4
#pragma unroll
            for (int j = 0; j < 4; j++) {
                int idx = tid + j * 256;
                cpasync16(swb + (unsigned)idx * 16,
                          s + (size_t)(hh * 128 + (idx >> 5)) * 32 + (idx & 31));
            }
            cpcommit();
        }
        for (int kb = 0; kb < 4; kb++) {
            if (kb < 3) {
                const float4* s = (const float4*)W2;
                unsigned dst = swb + ((kb + 1) & 1) * 16384u;
#pragma unroll
                for (int j = 0; j < 4; j++) {
                    int idx = tid + j * 256;
                    cpasync16(dst + (unsigned)idx * 16,
                              s + (size_t)(hh * 128 + (kb + 1) * 32 + (idx >> 5)) * 32 + (idx & 31));
                }
                cpcommit();
                cpwait1();
            } else cpwait0();
            __syncthreads();
            const float* wb = sW + (kb & 1) * 4096;
#pragma unroll
            for (int kk = 0; kk < 32; kk++) {
                float av[4];
#pragma unroll
                for (int r = 0; r < 4; r++) av[r] = sA[(ty * 4 + r) * HH + kb * 32 + kk];
#pragma unroll
                for (int q = 0; q < 2; q++) {
                    float4 w = ((const float4*)wb)[kk * 32 + q * 16 + tx];
#pragma unroll
                    for (int r = 0; r < 4; r++) {
                        acc2[r][q * 4 + 0] = fmaf(av[r], w.x, acc2[r][q * 4 + 0]);
                        acc2[r][q * 4 + 1] = fmaf(av[r], w.y, acc2[r][q * 4 + 1]);
                        acc2[r][q * 4 + 2] = fmaf(av[r], w.z, acc2[r][q * 4 + 2]);
                        acc2[r][q * 4 + 3] = fmaf(av[r], w.w, acc2[r][q * 4 + 3]);
                    }
                }
            }
            __syncthreads();
        }
    }

    // x = F + b2 + H -> sA (64 x 128)
#pragma unroll
    for (int q = 0; q < 2; q++)
#pragma unroll
        for (int u = 0; u < 4; u++) {
            int c = q * 64 + tx * 4 + u;
            float bb = b2[c];
#pragma unroll
            for (int r = 0; r < 4; r++) {
                int t = ty * 4 + r;
                sA[t * HH + c] = acc2[r][q * 4 + u] + bb + sH[t * HH + c];
            }
        }
    __syncthreads();

    // LayerNorm -> sH
    {
        int warp = tid >> 5, lane = tid & 31;
        for (int tt = warp * 8; tt < warp * 8 + 8; tt++) {
            float4 x = ((const float4*)sA)[tt * 32 + lane];
            float s1 = x.x + x.y + x.z + x.w;
            float s2 = fmaf(x.x, x.x, fmaf(x.y, x.y, fmaf(x.z, x.z, x.w * x.w)));
#pragma unroll
            for (int o = 16; o; o >>= 1) {
                s1 += __shfl_xor_sync(0xffffffffu, s1, o);
                s2 += __shfl_xor_sync(0xffffffffu, s2, o);
            }
            float mu  = s1 * (1.f / HH);
            float var = s2 * (1.f / HH) - mu * mu;
            float rs  = rsqrtf(var + 1e-5f);
            float4 gg = ((const float4*)lng)[lane];
            float4 bb = ((const float4*)lnb)[lane];
            float4 o;
            o.x = (x.x - mu) * rs * gg.x + bb.x;
            o.y = (x.y - mu) * rs * gg.y + bb.y;
            o.z = (x.z - mu) * rs * gg.z + bb.z;
            o.w = (x.w - mu) * rs * gg.w + bb.w;
            ((float4*)sH)[tt * 32 + lane] = o;
        }
    }
    __syncthreads();

    // ---- GEMM3: K = HN @ Wkp  (64x128x128), same staging
    float acc3[4][8];
#pragma unroll
    for (int r = 0; r < 4; r++)
#pragma unroll
        for (int c = 0; c < 8; c++) acc3[r][c] = 0.f;

    {
        const float4* s = (const float4*)Wkp;   // row = 32 float4
#pragma unroll
        for (int j = 0; j < 4; j++) {
            int idx = tid + j * 256;
            cpasync16(swb + (unsigned)idx * 16,
                      s + (size_t)(idx >> 5) * 32 + (idx & 31));
        }
        cpcommit();
    }
    for (int kb = 0; kb < 4; kb++) {
        if (kb < 3) {
            const float4* s = (const float4*)Wkp;
            unsigned dst = swb + ((kb + 1) & 1) * 16384u;
#pragma unroll
            for (int j = 0; j < 4; j++) {
                int idx = tid + j * 256;
                cpasync16(dst + (unsigned)idx * 16,
                          s + (size_t)((kb + 1) * 32 + (idx >> 5)) * 32 + (idx & 31));
            }
            cpcommit();
            cpwait1();
        } else cpwait0();
        __syncthreads();
        const float* wb = sW + (kb & 1) * 4096;
#pragma unroll
        for (int kk = 0; kk < 32; kk++) {
            float hv[4];
#pragma unroll
            for (int r = 0; r < 4; r++) hv[r] = sH[(ty * 4 + r) * HH + kb * 32 + kk];
#pragma unroll
            for (int q = 0; q < 2; q++) {
                float4 w = ((const float4*)wb)[kk * 32 + q * 16 + tx];
#pragma unroll
                for (int r = 0; r < 4; r++) {
                    acc3[r][q * 4 + 0] = fmaf(hv[r], w.x, acc3[r][q * 4 + 0]);
                    acc3[r][q * 4 + 1] = fmaf(hv[r], w.y, acc3[r][q * 4 + 1]);
                    acc3[r][q * 4 + 2] = fmaf(hv[r], w.z, acc3[r][q * 4 + 2]);
                    acc3[r][q * 4 + 3] = fmaf(hv[r], w.w, acc3[r][q * 4 + 3]);
                }
            }
        }
        __syncthreads();
    }
    // write raw K into sA
#pragma unroll
    for (int q = 0; q < 2; q++)
#pragma unroll
        for (int u = 0; u < 4; u++) {
            int c = q * 64 + tx * 4 + u;
#pragma unroll
            for (int r = 0; r < 4; r++)
                sA[(ty * 4 + r) * HH + c] = acc3[r][q * 4 + u];
        }
    __syncthreads();

    // per-token norms
    {
        int warp = tid >> 5, lane = tid & 31;
        for (int tt = warp * 8; tt < warp * 8 + 8; tt++) {
            float4 x = ((const float4*)sA)[tt * 32 + lane];
            float ss = fmaf(x.x, x.x, fmaf(x.y, x.y, fmaf(x.z, x.z, x.w * x.w)));
#pragma unroll
            for (int o = 16; o; o >>= 1) ss += __shfl_xor_sync(0xffffffffu, ss, o);
            if (lane == 0) {
                float n = fmaxf(sqrtf(ss), 1e-12f);
                g_nrm[t0 + tt] = n;
                sInv[tt] = 1.f / n;
            }
        }
    }
    __syncthreads();

    // write normalized kn
    {
        float4* gk = (float4*)g_k;
        const float4* s = (const float4*)sA;
        for (int idx = tid; idx < TOK * 32; idx += 256) {
            float inv = sInv[idx >> 5];
            float4 v = s[idx];
            v.x *= inv; v.y *= inv; v.z *= inv; v.w *= inv;
            gk[(size_t)t0 * 32 + idx] = v;
        }
    }
}

// ---------------------------------------------------------------------------
// Kernel B (R6 verbatim): one warp = one (batch,row), 4096 warps.
// ---------------------------------------------------------------------------
__global__ void __launch_bounds__(256) kScan()
{
    const int warp = threadIdx.x >> 5, lane = threadIdx.x & 31;
    const int b = blockIdx.x >> 4;
    const int i = ((blockIdx.x & 15) << 3) + warp;

    const float*      kbase = g_k + (size_t)b * LL * HH;
    const ulonglong2* kp    = (const ulonglong2*)kbase + lane;
    const float*      np    = g_nrm + b * LL;
    const float*      kip   = kbase + i;

    ull m01 = 0ULL, m23 = 0ULL;

    ulonglong2 cur = __ldg(kp);
    float kni = __ldg(kip);
    float nrm = __ldg(np);

    for (int t = 0; t < LL - 1; t++) {
        ulonglong2 nxt = __ldg(&kp[(size_t)(t + 1) * 32]);
        float kni_n = __ldg(&kip[(size_t)(t + 1) * HH]);
        float nrm_n = __ldg(&np[t + 1]);

        ull d = f2fma(m01, cur.x, 0ULL);
        d = f2fma(m23, cur.y, d);
        float lo, hi; upk2(d, lo, hi);
        float p = lo + hi;
        p += __shfl_xor_sync(0xffffffffu, p, 16);
        p += __shfl_xor_sync(0xffffffffu, p, 8);
        p += __shfl_xor_sync(0xffffffffu, p, 4);
        p += __shfl_xor_sync(0xffffffffu, p, 2);
        p += __shfl_xor_sync(0xffffffffu, p, 1);

        float c = fmaf(kni, nrm, -p);
        ull cd = pk2(c, c);
        m01 = f2fma(cd, cur.x, m01);
        m23 = f2fma(cd, cur.y, m23);

        cur = nxt; kni = kni_n; nrm = nrm_n;
    }

    ull d = f2fma(m01, cur.x, 0ULL);
    d = f2fma(m23, cur.y, d);
    float lo, hi; upk2(d, lo, hi);
    float p = lo + hi;
    p += __shfl_xor_sync(0xffffffffu, p, 16);
    p += __shfl_xor_sync(0xffffffffu, p, 8);
    p += __shfl_xor_sync(0xffffffffu, p, 4);
    p += __shfl_xor_sync(0xffffffffu, p, 2);
    p += __shfl_xor_sync(0xffffffffu, p, 1);
    if (lane == 0) g_read[b * HH + i] = p * nrm;
}

// ---------------------------------------------------------------------------
__global__ void __launch_bounds__(256) kC(const float* __restrict__ Wrp,
                                          const float* __restrict__ brp)
{
    int idx = blockIdx.x * 256 + threadIdx.x;
    if (idx >= BB * HH) return;
    int b = idx >> 7, d = idx & 127;
    float s = brp[d];
#pragma unroll 8
    for (int h = 0; h < HH; h++)
        s = fmaf(__ldg(&g_read[b * HH + h]), __ldg(&Wrp[h * HH + d]), s);
    g_r2[idx] = s;
}

// ---------------------------------------------------------------------------
__global__ void __launch_bounds__(256) kD(const float* __restrict__ Wout,
                                          const float* __restrict__ bout,
                                          float* __restrict__ out)
{
    __shared__ float sr[BB * HH];
    for (int idx = threadIdx.x; idx < BB * HH; idx += 256) sr[idx] = g_r2[idx];
    __syncthreads();
    int v = blockIdx.x * 256 + threadIdx.x;
    if (v >= VV) return;

    float acc[BB];
#pragma unroll
    for (int b = 0; b < BB; b++) acc[b] = 0.f;

#pragma unroll 1
    for (int h0 = 0; h0 < HH; h0 += 8) {
        float wv[8];
#pragma unroll
        for (int u = 0; u < 8; u++)
            wv[u] = __ldg(&Wout[(size_t)(h0 + u) * VV + v]);
#pragma unroll
        for (int u = 0; u < 8; u++)
#pragma unroll
            for (int b = 0; b < BB; b++)
                acc[b] = fmaf(sr[b * HH + h0 + u], wv[u], acc[b]);
    }
    float bo = __ldg(&bout[v]);
#pragma unroll
    for (int b = 0; b < BB; b++)
        out[(size_t)b * VV + v] = acc[b] + bo;
}

// ---------------------------------------------------------------------------
extern "C" void kernel_launch(void* const* d_in, const int* in_sizes, int n_in,
                              void* d_out, int out_size)
{
    const int*   seq   = (const int*)d_in[0];
    const float* embed = (const float*)d_in[1];
    const float* W1    = (const float*)d_in[2];
    const float* b1    = (const float*)d_in[3];
    const float* W2    = (const float*)d_in[4];
    const float* b2    = (const float*)d_in[5];
    const float* lng   = (const float*)d_in[6];
    const float* lnb   = (const float*)d_in[7];
    const float* Wkp   = (const float*)d_in[8];
    const float* Wrp   = (const float*)d_in[9];
    const float* brp   = (const float*)d_in[10];
    const float* Wout  = (const float*)d_in[11];
    const float* bout  = (const float*)d_in[12];
    float* out = (float*)d_out;

    cudaFuncSetAttribute(kA, cudaFuncAttributeMaxDynamicSharedMemorySize, 98304);

    kA<<<NTOK / TOK, 256, 98304>>>(seq, embed, W1, b1, W2, b2, lng, lnb, Wkp);
    kScan<<<(BB * HH) / 8, 256>>>();
    kC<<<(BB * HH + 255) / 256, 256>>>(Wrp, brp);
    kD<<<(VV + 255) / 256, 256>>>(Wout, bout, out);
}